// round 14
// baseline (speedup 1.0000x reference)
#include <cuda_runtime.h>
#include <math.h>
#include <stdint.h>

// ---------------- problem constants ----------------
#define BATCH 256
#define CIN   22
#define WIN   9
#define SEG   125
#define OUTC  64
#define KS    63
#define NCLS  4
#define TLEN  1125          // WIN*SEG
#define NEDGE 231           // 22*21/2

// ---------------- device scratch ----------------
__device__ float g_W1[OUTC * CIN];
__device__ float g_sb[OUTC];
__device__ float g_tg[OUTC];
__device__ float g_tb[OUTC];
__device__ float g_Atb2[WIN * WIN];
__device__ float g_fcA[NCLS * OUTC * WIN];
__device__ float g_xb[BATCH * CIN * TLEN];
__device__ float g_w3[CIN * 2048];               // bf16x2 weights in m16n8k16 B-frag layout
__device__ float g_C[OUTC * (KS + 1)];           // bias cumsum [o][64]
__device__ float g_pool[576 * 2 * BATCH];        // TRANSPOSED: [o*9+w][bb]
__device__ float g_xmean[BATCH * CIN];

// ---------------- helpers ----------------
__device__ __forceinline__ float gelu_exact(float x) {
    return 0.5f * x * (1.f + erff(x * 0.70710678118654752440f));
}
// pack two floats into bf16x2: lo -> bits[15:0], hi -> bits[31:16]
__device__ __forceinline__ uint32_t pack_bf(float lo, float hi) {
    uint32_t r; asm("cvt.rn.bf16x2.f32 %0, %1, %2;" : "=r"(r) : "f"(hi), "f"(lo)); return r;
}
// m16n8k16 bf16 warp MMA (row.col), D += A*B
__device__ __forceinline__ void mma16(float* d, const uint32_t* a, uint32_t b0, uint32_t b1) {
    asm volatile(
        "mma.sync.aligned.m16n8k16.row.col.f32.bf16.bf16.f32 "
        "{%0,%1,%2,%3}, {%4,%5,%6,%7}, {%8,%9}, {%0,%1,%2,%3};"
        : "+f"(d[0]), "+f"(d[1]), "+f"(d[2]), "+f"(d[3])
        : "r"(a[0]), "r"(a[1]), "r"(a[2]), "r"(a[3]), "r"(b0), "r"(b1));
}

// ============================================================
// Kernel 0: small precompute (+ zero g_xmean for the fused mean)
// ============================================================
__global__ void k_prep(const float* __restrict__ ew,
                       const float* __restrict__ sconv_w,
                       const float* __restrict__ sbn_g, const float* __restrict__ sbn_b,
                       const float* __restrict__ sbn_m, const float* __restrict__ sbn_v,
                       const float* __restrict__ tbn_g, const float* __restrict__ tbn_b,
                       const float* __restrict__ tbn_m, const float* __restrict__ tbn_v,
                       const float* __restrict__ adj_after,
                       const float* __restrict__ adj_before,
                       const float* __restrict__ fc_a_w,
                       float* __restrict__ out)
{
    __shared__ float A[484], As[484], As2[484], d22[22];
    __shared__ float Mt[81], At[81], At2[81], d9[9];
    const int tid = threadIdx.x;

    for (int idx = tid; idx < BATCH * CIN; idx += 256) g_xmean[idx] = 0.f;

    for (int idx = tid; idx < 484; idx += 256) {
        int i = idx / 22, j = idx - i * 22;
        A[idx] = (i == j) ? 1.f : 0.f;
    }
    __syncthreads();
    if (tid < NEDGE) {
        int e = tid, i = 1, base = 0;
        while (e >= base + i) { base += i; i++; }
        int j = e - base;
        float v = ew[tid];
        A[i * 22 + j] = v; A[j * 22 + i] = v;
    }
    __syncthreads();
    if (tid < 22) {
        float s = 0.f;
        for (int j = 0; j < 22; j++) s += A[tid * 22 + j];
        d22[tid] = rsqrtf(s);
    }
    __syncthreads();
    for (int idx = tid; idx < 484; idx += 256) {
        int i = idx / 22, j = idx - i * 22;
        As[idx] = A[idx] * d22[i] * d22[j];
    }
    __syncthreads();
    for (int idx = tid; idx < 484; idx += 256) {
        out[1024 + idx] = As[idx];
        out[1670 + idx] = As[idx];
        int i = idx / 22, j = idx - i * 22;
        float s = 0.f;
        for (int k = 0; k < 22; k++) s += As[i * 22 + k] * As[k * 22 + j];
        As2[idx] = s;
    }
    __syncthreads();

    for (int idx = tid; idx < OUTC * CIN; idx += 256) {
        int o = idx / CIN, c = idx - o * CIN;
        float s = 0.f;
        for (int c2 = 0; c2 < 22; c2++) s += sconv_w[o * CIN + c2] * As2[c2 * 22 + c];
        float sg = sbn_g[o] * rsqrtf(sbn_v[o] + 1e-5f);
        g_W1[idx] = sg * s;
    }
    if (tid < OUTC) {
        float sg = sbn_g[tid] * rsqrtf(sbn_v[tid] + 1e-5f);
        g_sb[tid] = sbn_b[tid] - sbn_m[tid] * sg;
        float tg = tbn_g[tid] * rsqrtf(tbn_v[tid] + 1e-5f);
        g_tg[tid] = tg;
        g_tb[tid] = tbn_b[tid] - tbn_m[tid] * tg;
    }

    if (tid < 81) {
        int i = tid / 9, j = tid - i * 9;
        Mt[tid] = 0.5f * (adj_after[i * 9 + j] + adj_after[j * 9 + i]);
    }
    __syncthreads();
    if (tid < 9) {
        float s = 0.f;
        for (int j = 0; j < 9; j++) s += Mt[tid * 9 + j];
        d9[tid] = rsqrtf(s);
    }
    __syncthreads();
    if (tid < 81) {
        int i = tid / 9, j = tid - i * 9;
        At[tid] = Mt[tid] * d9[i] * d9[j];
        out[1508 + tid] = At[tid];
    }
    __syncthreads();
    if (tid < 81) {
        int i = tid / 9, j = tid - i * 9;
        float s = 0.f;
        for (int k = 0; k < 9; k++) s += At[i * 9 + k] * At[k * 9 + j];
        At2[tid] = s;
    }
    __syncthreads();
    for (int idx = tid; idx < NCLS * OUTC * WIN; idx += 256) {
        int n = idx / (OUTC * WIN);
        int rem = idx - n * OUTC * WIN;
        int o = rem / WIN, w = rem - o * WIN;
        float s = 0.f;
        for (int wp = 0; wp < 9; wp++) s += fc_a_w[n * 576 + o * 9 + wp] * At2[wp * 9 + w];
        g_fcA[idx] = s;
    }
    __syncthreads();

    if (tid < 81) {
        int i = tid / 9, j = tid - i * 9;
        Mt[tid] = 0.5f * (adj_before[i * 9 + j] + adj_before[j * 9 + i]);
    }
    __syncthreads();
    if (tid < 9) {
        float s = 0.f;
        for (int j = 0; j < 9; j++) s += Mt[tid * 9 + j];
        d9[tid] = rsqrtf(s);
    }
    __syncthreads();
    if (tid < 81) {
        int i = tid / 9, j = tid - i * 9;
        At[tid] = Mt[tid] * d9[i] * d9[j];
        out[1589 + tid] = At[tid];
    }
    __syncthreads();
    if (tid < 81) {
        int i = tid / 9, j = tid - i * 9;
        float s = 0.f;
        for (int k = 0; k < 9; k++) s += At[i * 9 + k] * At[k * 9 + j];
        g_Atb2[tid] = s;
    }
}

// ============================================================
// k_fold: bf16 B-fragments DIRECTLY from tconv_w (x) g_W1,
// plus bias q + IN-BLOCK cumsum -> g_C in the tail blocks.
// ============================================================
__global__ void k_fold(const float* __restrict__ tconv_w) {
    __shared__ float sW1[OUTC * CIN];
    __shared__ float ssb[OUTC];
    __shared__ float sq[4][64];
    const int blk = blockIdx.x, tid = threadIdx.x;
    for (int i = tid; i < OUTC * CIN; i += 256) sW1[i] = g_W1[i];
    if (tid < OUTC) ssb[tid] = g_sb[tid];
    __syncthreads();

    if (blk < 176) {
        int idx = blk * 256 + tid;                 // < CIN*2048 = 45056
        int c = idx >> 11;
        int rem = idx & 2047;
        int chunk = rem >> 9;
        int ntg = (rem >> 6) & 7;
        int lane = (rem >> 1) & 31;
        int r = rem & 1;
        int g = lane >> 2, tig = lane & 3;
        int o = ntg * 8 + g;
        int k0 = chunk * 16 + 2 * tig + 8 * r;
        const float* tw = tconv_w + o * OUTC * KS;
        float s0 = 0.f, s1 = 0.f;
        const bool v0ok = (k0 < KS), v1ok = (k0 + 1 < KS);
        #pragma unroll 8
        for (int i = 0; i < OUTC; i++) {
            float w1 = sW1[i * CIN + c];
            if (v0ok) s0 += tw[i * KS + k0] * w1;
            if (v1ok) s1 += tw[i * KS + k0 + 1] * w1;
        }
        ((uint32_t*)g_w3)[idx] = pack_bf(s0, s1);
    } else {
        int ol = tid >> 6, k = tid & 63;
        int o = (blk - 176) * 4 + ol;
        if (k < KS) {
            const float* wp = tconv_w + o * OUTC * KS + k;
            float s = 0.f;
            #pragma unroll 8
            for (int i = 0; i < OUTC; i++)
                s += wp[i * KS] * ssb[i];
            sq[ol][k] = s;
        }
        __syncthreads();
        if (k == 0) {
            float cum = 0.f;
            g_C[o * (KS + 1)] = 0.f;
            for (int kk = 0; kk < KS; kk++) {
                cum += sq[ol][kk];
                g_C[o * (KS + 1) + kk + 1] = cum;
            }
        }
    }
}

// ============================================================
// branch-B time mix (view regrouping) + FUSED branch-C mean partials
// ============================================================
__global__ void k_xb(const float* __restrict__ x) {
    __shared__ float red[4 * WIN];
    const int bk = blockIdx.x;
    const int b = bk / CIN, r = bk - b * CIN;
    const int s = threadIdx.x;
    const int lane = s & 31, wid = s >> 5;
    const bool act = (s < SEG);
    float v[WIN];
    #pragma unroll
    for (int pp = 0; pp < WIN; pp++) {
        int m = 22 * pp + r;
        int c = m / 9, w = m - c * 9;
        v[pp] = act ? x[((size_t)b * CIN + c) * TLEN + w * SEG + s] : 0.f;
    }
    #pragma unroll
    for (int pp = 0; pp < WIN; pp++) {
        float t = v[pp];
        #pragma unroll
        for (int m = 16; m >= 1; m >>= 1) t += __shfl_xor_sync(0xffffffffu, t, m);
        if (lane == 0) red[wid * WIN + pp] = t;
    }
    __syncthreads();
    if (s < WIN) {
        float t = red[s] + red[WIN + s] + red[2 * WIN + s] + red[3 * WIN + s];
        int m = 22 * s + r;
        int c = m / 9;
        atomicAdd(&g_xmean[b * CIN + c], t * (1.f / (float)TLEN));
    }
    if (act) {
        float* dst = g_xb + ((size_t)b * CIN + r) * TLEN + s;
        #pragma unroll
        for (int p = 0; p < WIN; p++) {
            float a = 0.f;
            #pragma unroll
            for (int pp = 0; pp < WIN; pp++)
                a = fmaf(g_Atb2[p * 9 + pp], v[pp], a);
            dst[p * SEG] = a;
        }
    }
}

// ============================================================
// MAIN: bf16 m16n8k16 mma.sync conv — 256 threads, 8 warps, 1 tile/CTA.
// Warp (wm in 0..3, wn in 0..1): 32 t x 32 o. acc = 32 regs/thread.
// grid (9, 512) unchanged.
// ============================================================
#define DYN_SMEM ((4224 + 4096 + 256) * 4)   // y pairs + 2x weight buf (=C table) + s_part[4][64]

__global__ void __launch_bounds__(256) k_conv5(const float* __restrict__ x) {
    extern __shared__ float sm[];
    float* y_s = sm;                  // [22][192] bf16x2 pairs
    float* w_s = sm + 4224;           // [2][2048] b32 fragments; reused as C table [64][64]
    float* s_part = sm + 4224 + 4096; // [4][64]
    __shared__ float s_q[64], s_tg[64], s_tb[64];

    const int w = blockIdx.x;
    const int bb = blockIdx.y;
    const int tid = threadIdx.x;
    const int wid = tid >> 5, lane = tid & 31;
    const int wm = wid & 3, wn = wid >> 2;
    const int g = lane >> 2, tig = lane & 3;
    const int t0 = w * SEG - 31;
    const float* src = ((bb >> 8) ? g_xb : x) + (size_t)(bb & 255) * CIN * TLEN;

    // y halo tile as overlapping bf16x2 pairs (187 valid positions, rest zero)
    uint32_t* yu = (uint32_t*)y_s;
    for (int idx = tid; idx < CIN * 192; idx += 256) {
        int c = idx / 192, tt = idx - c * 192;
        int gt = t0 + tt;
        float v0 = (gt >= 0 && gt < TLEN && tt < 187) ? src[(size_t)c * TLEN + gt] : 0.f;
        float v1 = (gt + 1 >= 0 && gt + 1 < TLEN && tt + 1 < 187) ? src[(size_t)c * TLEN + gt + 1] : 0.f;
        yu[idx] = pack_bf(v0, v1);
    }
    // first channel's weights
    {
        const float4* s4 = (const float4*)g_w3;
        float4* d4 = (float4*)w_s;
        #pragma unroll
        for (int j = 0; j < 2; j++) d4[j * 256 + tid] = s4[j * 256 + tid];
    }
    if (tid < 64) { s_q[tid] = g_C[tid * 64 + 63]; s_tg[tid] = g_tg[tid]; s_tb[tid] = g_tb[tid]; }
    __syncthreads();

    float acc[2][4][4];
    #pragma unroll
    for (int m = 0; m < 2; m++)
        #pragma unroll
        for (int nt = 0; nt < 4; nt++)
            #pragma unroll
            for (int j = 0; j < 4; j++) acc[m][nt][j] = 0.f;

    for (int c = 0; c < CIN; c++) {
        float4 pf[2];
        if (c < CIN - 1) {
            const float4* s4 = (const float4*)(g_w3 + (c + 1) * 2048);
            #pragma unroll
            for (int j = 0; j < 2; j++) pf[j] = s4[j * 256 + tid];
        }
        const uint32_t* ya = yu + c * 192 + wm * 32 + g + 2 * tig;
        const uint32_t* wb = (const uint32_t*)w_s + (c & 1) * 2048 + wn * 256 + lane * 2;

        #pragma unroll
        for (int chunk = 0; chunk < 4; chunk++) {
            uint32_t a[2][4];
            #pragma unroll
            for (int m = 0; m < 2; m++) {
                const uint32_t* p = ya + m * 16 + chunk * 16;
                uint32_t p0 = p[0], p1 = p[8], p2 = p[16];
                a[m][0] = p0; a[m][1] = p1; a[m][2] = p1; a[m][3] = p2;
            }
            #pragma unroll
            for (int nt = 0; nt < 4; nt++) {
                uint2 bv = *(const uint2*)(wb + chunk * 512 + nt * 64);
                #pragma unroll
                for (int m = 0; m < 2; m++)
                    mma16(acc[m][nt], a[m], bv.x, bv.y);
            }
        }
        __syncthreads();
        if (c < CIN - 1) {
            float4* d4 = (float4*)(w_s + ((c + 1) & 1) * 2048);
            #pragma unroll
            for (int j = 0; j < 2; j++) d4[j * 256 + tid] = pf[j];
            __syncthreads();
        }
    }

    // ---- epilogue ----
    const bool edge = (w == 0) || (w == WIN - 1);
    if (edge) {
        for (int j = tid; j < 4096; j += 256) w_s[j] = g_C[j];
    }
    __syncthreads();

    const int tg_base = w * SEG;
    #pragma unroll
    for (int nt = 0; nt < 4; nt++) {
        int o0 = wn * 32 + nt * 8 + 2 * tig, o1 = o0 + 1;
        float tg0 = s_tg[o0], tb0_ = s_tb[o0], tg1 = s_tg[o1], tb1_ = s_tb[o1];
        float q0 = s_q[o0], q1 = s_q[o1];
        float s0 = 0.f, s1 = 0.f;
        #pragma unroll
        for (int m = 0; m < 2; m++) {
            int t_a = wm * 32 + m * 16 + g;
            int t_b = t_a + 8;
            float b0a = q0, b1a = q1, b0b = q0, b1b = q1;
            if (edge) {
                int tag = tg_base + t_a;
                int kmin = 31 - tag; kmin = kmin < 0 ? 0 : kmin;
                int kx = 1156 - tag; kx = kx > 63 ? 63 : kx;
                b0a = w_s[o0 * 64 + kx] - w_s[o0 * 64 + kmin];
                b1a = w_s[o1 * 64 + kx] - w_s[o1 * 64 + kmin];
                int tbg = tag + 8;
                int kminb = 31 - tbg; kminb = kminb < 0 ? 0 : kminb;
                int kxb = 1156 - tbg; kxb = kxb > 63 ? 63 : kxb;
                b0b = w_s[o0 * 64 + kxb] - w_s[o0 * 64 + kminb];
                b1b = w_s[o1 * 64 + kxb] - w_s[o1 * 64 + kminb];
            }
            if (t_a < SEG) {
                s0 += gelu_exact(fmaf(acc[m][nt][0] + b0a, tg0, tb0_));
                s1 += gelu_exact(fmaf(acc[m][nt][1] + b1a, tg1, tb1_));
            }
            if (t_b < SEG) {
                s0 += gelu_exact(fmaf(acc[m][nt][2] + b0b, tg0, tb0_));
                s1 += gelu_exact(fmaf(acc[m][nt][3] + b1b, tg1, tb1_));
            }
        }
        s0 += __shfl_xor_sync(0xffffffffu, s0, 4);
        s0 += __shfl_xor_sync(0xffffffffu, s0, 8);
        s0 += __shfl_xor_sync(0xffffffffu, s0, 16);
        s1 += __shfl_xor_sync(0xffffffffu, s1, 4);
        s1 += __shfl_xor_sync(0xffffffffu, s1, 8);
        s1 += __shfl_xor_sync(0xffffffffu, s1, 16);
        if (g == 0) {
            s_part[wm * 64 + o0] = s0;
            s_part[wm * 64 + o1] = s1;
        }
    }
    __syncthreads();
    if (tid < 64)
        g_pool[(tid * 9 + w) * (2 * BATCH) + bb] =
            (s_part[tid] + s_part[64 + tid] + s_part[128 + tid] + s_part[192 + tid]) * 0.008f;
}

// ============================================================
// final FCs + fuse — parallel: 8 blocks x (32 b x 8 j-groups)
// ============================================================
__global__ void k_fc(const float* __restrict__ fc_a_b,
                     const float* __restrict__ fc_b_w, const float* __restrict__ fc_b_b,
                     const float* __restrict__ fc_c_w, const float* __restrict__ fc_c_b,
                     const float* __restrict__ fuse_w, const float* __restrict__ fuse_b,
                     float* __restrict__ out)
{
    __shared__ float sA[NCLS * 576];
    __shared__ float sB[NCLS * 576];
    __shared__ float red[256][8];
    const int tid = threadIdx.x;
    for (int idx = tid; idx < NCLS * 576; idx += 256) {
        sA[idx] = g_fcA[idx];
        sB[idx] = fc_b_w[idx];
    }
    __syncthreads();
    const int bl = tid & 31, jg = tid >> 5;
    const int b = blockIdx.x * 32 + bl;
    float la[4] = {0.f, 0.f, 0.f, 0.f}, lb[4] = {0.f, 0.f, 0.f, 0.f};
    const int j0 = jg * 72;
    for (int j = j0; j < j0 + 72; j++) {
        float va = g_pool[j * (2 * BATCH) + b];
        float vb = g_pool[j * (2 * BATCH) + BATCH + b];
        #pragma unroll
        for (int n = 0; n < 4; n++) {
            la[n] = fmaf(sA[n * 576 + j], va, la[n]);
            lb[n] = fmaf(sB[n * 576 + j], vb, lb[n]);
        }
    }
    #pragma unroll
    for (int n = 0; n < 4; n++) { red[tid][n] = la[n]; red[tid][4 + n] = lb[n]; }
    __syncthreads();
    if (jg == 0) {
        #pragma unroll
        for (int n = 0; n < 4; n++) { la[n] += fc_a_b[n]; lb[n] += fc_b_b[n]; }
        for (int gg = 1; gg < 8; gg++) {
            #pragma unroll
            for (int n = 0; n < 4; n++) {
                la[n] += red[gg * 32 + bl][n];
                lb[n] += red[gg * 32 + bl][4 + n];
            }
        }
        float lc[4];
        #pragma unroll
        for (int n = 0; n < 4; n++) lc[n] = fc_c_b[n];
        for (int c = 0; c < CIN; c++) {
            float v = g_xmean[b * CIN + c];
            #pragma unroll
            for (int n = 0; n < 4; n++) lc[n] = fmaf(fc_c_w[n * CIN + c], v, lc[n]);
        }
        #pragma unroll
        for (int n = 0; n < 4; n++) {
            float o = fuse_b[n];
            #pragma unroll
            for (int m = 0; m < 4; m++) {
                o = fmaf(fuse_w[n * 12 + m], la[m], o);
                o = fmaf(fuse_w[n * 12 + 4 + m], lb[m], o);
                o = fmaf(fuse_w[n * 12 + 8 + m], lc[m], o);
            }
            out[b * 4 + n] = o;
        }
    }
}

// ============================================================
// launch
// ============================================================
extern "C" void kernel_launch(void* const* d_in, const int* in_sizes, int n_in,
                              void* d_out, int out_size) {
    const float* x        = (const float*)d_in[0];
    const float* edge_w   = (const float*)d_in[1];
    const float* sconv_w  = (const float*)d_in[2];
    const float* sbn_g    = (const float*)d_in[3];
    const float* sbn_b    = (const float*)d_in[4];
    const float* sbn_m    = (const float*)d_in[5];
    const float* sbn_v    = (const float*)d_in[6];
    const float* tconv_w  = (const float*)d_in[7];
    const float* tbn_g    = (const float*)d_in[8];
    const float* tbn_b    = (const float*)d_in[9];
    const float* tbn_m    = (const float*)d_in[10];
    const float* tbn_v    = (const float*)d_in[11];
    const float* adj_a    = (const float*)d_in[12];
    const float* adj_b    = (const float*)d_in[13];
    const float* fc_a_w   = (const float*)d_in[14];
    const float* fc_a_b   = (const float*)d_in[15];
    const float* fc_b_w   = (const float*)d_in[16];
    const float* fc_b_b   = (const float*)d_in[17];
    const float* fc_c_w   = (const float*)d_in[18];
    const float* fc_c_b   = (const float*)d_in[19];
    const float* fuse_w   = (const float*)d_in[20];
    const float* fuse_b   = (const float*)d_in[21];
    float* out = (float*)d_out;

    cudaFuncSetAttribute(k_conv5, cudaFuncAttributeMaxDynamicSharedMemorySize, DYN_SMEM);

    k_prep<<<1, 256>>>(edge_w, sconv_w, sbn_g, sbn_b, sbn_m, sbn_v,
                       tbn_g, tbn_b, tbn_m, tbn_v, adj_a, adj_b, fc_a_w, out);
    k_fold<<<192, 256>>>(tconv_w);
    k_xb<<<BATCH * CIN, 128>>>(x);
    k_conv5<<<dim3(WIN, 2 * BATCH), 256, DYN_SMEM>>>(x);
    k_fc<<<8, 256>>>(fc_a_b, fc_b_w, fc_b_b, fc_c_w, fc_c_b, fuse_w, fuse_b, out);
}

// round 15
// speedup vs baseline: 1.1069x; 1.1069x over previous
#include <cuda_runtime.h>
#include <math.h>
#include <stdint.h>

// ---------------- problem constants ----------------
#define BATCH 256
#define CIN   22
#define WIN   9
#define SEG   125
#define OUTC  64
#define KS    63
#define NCLS  4
#define TLEN  1125          // WIN*SEG
#define NEDGE 231           // 22*21/2

// ---------------- device scratch ----------------
__device__ float g_W1[OUTC * CIN];
__device__ float g_sb[OUTC];
__device__ float g_tg[OUTC];
__device__ float g_tb[OUTC];
__device__ float g_Atb2[WIN * WIN];
__device__ float g_fcA[NCLS * OUTC * WIN];
__device__ float g_xb[BATCH * CIN * TLEN];
__device__ float g_w3[CIN * 2048];               // bf16x2 weights in m16n8k16 B-frag layout
__device__ float g_C[OUTC * (KS + 1)];           // bias cumsum [o][64]
__device__ float g_pool[576 * 2 * BATCH];        // TRANSPOSED: [o*9+w][bb]
__device__ float g_xmean[BATCH * CIN];

// ---------------- helpers ----------------
__device__ __forceinline__ float gelu_exact(float x) {
    return 0.5f * x * (1.f + erff(x * 0.70710678118654752440f));
}
// pack two floats into bf16x2: lo -> bits[15:0], hi -> bits[31:16]
__device__ __forceinline__ uint32_t pack_bf(float lo, float hi) {
    uint32_t r; asm("cvt.rn.bf16x2.f32 %0, %1, %2;" : "=r"(r) : "f"(hi), "f"(lo)); return r;
}
// m16n8k16 bf16 warp MMA (row.col), D += A*B
__device__ __forceinline__ void mma16(float* d, const uint32_t* a, uint32_t b0, uint32_t b1) {
    asm volatile(
        "mma.sync.aligned.m16n8k16.row.col.f32.bf16.bf16.f32 "
        "{%0,%1,%2,%3}, {%4,%5,%6,%7}, {%8,%9}, {%0,%1,%2,%3};"
        : "+f"(d[0]), "+f"(d[1]), "+f"(d[2]), "+f"(d[3])
        : "r"(a[0]), "r"(a[1]), "r"(a[2]), "r"(a[3]), "r"(b0), "r"(b1));
}

// ============================================================
// Kernel 0: small precompute (+ zero g_xmean for the fused mean)
// ============================================================
__global__ void k_prep(const float* __restrict__ ew,
                       const float* __restrict__ sconv_w,
                       const float* __restrict__ sbn_g, const float* __restrict__ sbn_b,
                       const float* __restrict__ sbn_m, const float* __restrict__ sbn_v,
                       const float* __restrict__ tbn_g, const float* __restrict__ tbn_b,
                       const float* __restrict__ tbn_m, const float* __restrict__ tbn_v,
                       const float* __restrict__ adj_after,
                       const float* __restrict__ adj_before,
                       const float* __restrict__ fc_a_w,
                       float* __restrict__ out)
{
    __shared__ float A[484], As[484], As2[484], d22[22];
    __shared__ float Mt[81], At[81], At2[81], d9[9];
    const int tid = threadIdx.x;

    for (int idx = tid; idx < BATCH * CIN; idx += 256) g_xmean[idx] = 0.f;

    for (int idx = tid; idx < 484; idx += 256) {
        int i = idx / 22, j = idx - i * 22;
        A[idx] = (i == j) ? 1.f : 0.f;
    }
    __syncthreads();
    if (tid < NEDGE) {
        int e = tid, i = 1, base = 0;
        while (e >= base + i) { base += i; i++; }
        int j = e - base;
        float v = ew[tid];
        A[i * 22 + j] = v; A[j * 22 + i] = v;
    }
    __syncthreads();
    if (tid < 22) {
        float s = 0.f;
        for (int j = 0; j < 22; j++) s += A[tid * 22 + j];
        d22[tid] = rsqrtf(s);
    }
    __syncthreads();
    for (int idx = tid; idx < 484; idx += 256) {
        int i = idx / 22, j = idx - i * 22;
        As[idx] = A[idx] * d22[i] * d22[j];
    }
    __syncthreads();
    for (int idx = tid; idx < 484; idx += 256) {
        out[1024 + idx] = As[idx];
        out[1670 + idx] = As[idx];
        int i = idx / 22, j = idx - i * 22;
        float s = 0.f;
        for (int k = 0; k < 22; k++) s += As[i * 22 + k] * As[k * 22 + j];
        As2[idx] = s;
    }
    __syncthreads();

    for (int idx = tid; idx < OUTC * CIN; idx += 256) {
        int o = idx / CIN, c = idx - o * CIN;
        float s = 0.f;
        for (int c2 = 0; c2 < 22; c2++) s += sconv_w[o * CIN + c2] * As2[c2 * 22 + c];
        float sg = sbn_g[o] * rsqrtf(sbn_v[o] + 1e-5f);
        g_W1[idx] = sg * s;
    }
    if (tid < OUTC) {
        float sg = sbn_g[tid] * rsqrtf(sbn_v[tid] + 1e-5f);
        g_sb[tid] = sbn_b[tid] - sbn_m[tid] * sg;
        float tg = tbn_g[tid] * rsqrtf(tbn_v[tid] + 1e-5f);
        g_tg[tid] = tg;
        g_tb[tid] = tbn_b[tid] - tbn_m[tid] * tg;
    }

    if (tid < 81) {
        int i = tid / 9, j = tid - i * 9;
        Mt[tid] = 0.5f * (adj_after[i * 9 + j] + adj_after[j * 9 + i]);
    }
    __syncthreads();
    if (tid < 9) {
        float s = 0.f;
        for (int j = 0; j < 9; j++) s += Mt[tid * 9 + j];
        d9[tid] = rsqrtf(s);
    }
    __syncthreads();
    if (tid < 81) {
        int i = tid / 9, j = tid - i * 9;
        At[tid] = Mt[tid] * d9[i] * d9[j];
        out[1508 + tid] = At[tid];
    }
    __syncthreads();
    if (tid < 81) {
        int i = tid / 9, j = tid - i * 9;
        float s = 0.f;
        for (int k = 0; k < 9; k++) s += At[i * 9 + k] * At[k * 9 + j];
        At2[tid] = s;
    }
    __syncthreads();
    for (int idx = tid; idx < NCLS * OUTC * WIN; idx += 256) {
        int n = idx / (OUTC * WIN);
        int rem = idx - n * OUTC * WIN;
        int o = rem / WIN, w = rem - o * WIN;
        float s = 0.f;
        for (int wp = 0; wp < 9; wp++) s += fc_a_w[n * 576 + o * 9 + wp] * At2[wp * 9 + w];
        g_fcA[idx] = s;
    }
    __syncthreads();

    if (tid < 81) {
        int i = tid / 9, j = tid - i * 9;
        Mt[tid] = 0.5f * (adj_before[i * 9 + j] + adj_before[j * 9 + i]);
    }
    __syncthreads();
    if (tid < 9) {
        float s = 0.f;
        for (int j = 0; j < 9; j++) s += Mt[tid * 9 + j];
        d9[tid] = rsqrtf(s);
    }
    __syncthreads();
    if (tid < 81) {
        int i = tid / 9, j = tid - i * 9;
        At[tid] = Mt[tid] * d9[i] * d9[j];
        out[1589 + tid] = At[tid];
    }
    __syncthreads();
    if (tid < 81) {
        int i = tid / 9, j = tid - i * 9;
        float s = 0.f;
        for (int k = 0; k < 9; k++) s += At[i * 9 + k] * At[k * 9 + j];
        g_Atb2[tid] = s;
    }
}

// ============================================================
// k_fx: MERGED fold + xb (independent; co-scheduled in one launch)
// blocks 0..175:    bf16 B-fragments from tconv_w (x) g_W1
// blocks 176..191:  bias q + in-block cumsum -> g_C
// blocks 192..3007: branch-B time mix, TWO (b,r) rows per block
//                   (half = tid>>7, 128-thread semantics per half)
//                   + fused branch-C mean partials
// ============================================================
__global__ void k_fx(const float* __restrict__ tconv_w,
                     const float* __restrict__ x) {
    __shared__ float sW1[OUTC * CIN];
    __shared__ float ssb[OUTC];
    __shared__ float sq[4][64];
    __shared__ float red2[2][4 * WIN];
    const int blk = blockIdx.x, tid = threadIdx.x;

    if (blk < 192) {
        for (int i = tid; i < OUTC * CIN; i += 256) sW1[i] = g_W1[i];
        if (tid < OUTC) ssb[tid] = g_sb[tid];
        __syncthreads();

        if (blk < 176) {
            int idx = blk * 256 + tid;                 // < CIN*2048 = 45056
            int c = idx >> 11;
            int rem = idx & 2047;
            int chunk = rem >> 9;
            int ntg = (rem >> 6) & 7;
            int lane = (rem >> 1) & 31;
            int r = rem & 1;
            int g = lane >> 2, tig = lane & 3;
            int o = ntg * 8 + g;
            int k0 = chunk * 16 + 2 * tig + 8 * r;
            const float* tw = tconv_w + o * OUTC * KS;
            float s0 = 0.f, s1 = 0.f;
            const bool v0ok = (k0 < KS), v1ok = (k0 + 1 < KS);
            #pragma unroll 8
            for (int i = 0; i < OUTC; i++) {
                float w1 = sW1[i * CIN + c];
                if (v0ok) s0 += tw[i * KS + k0] * w1;
                if (v1ok) s1 += tw[i * KS + k0 + 1] * w1;
            }
            ((uint32_t*)g_w3)[idx] = pack_bf(s0, s1);
        } else {
            int ol = tid >> 6, k = tid & 63;
            int o = (blk - 176) * 4 + ol;
            if (k < KS) {
                const float* wp = tconv_w + o * OUTC * KS + k;
                float s = 0.f;
                #pragma unroll 8
                for (int i = 0; i < OUTC; i++)
                    s += wp[i * KS] * ssb[i];
                sq[ol][k] = s;
            }
            __syncthreads();
            if (k == 0) {
                float cum = 0.f;
                g_C[o * (KS + 1)] = 0.f;
                for (int kk = 0; kk < KS; kk++) {
                    cum += sq[ol][kk];
                    g_C[o * (KS + 1) + kk + 1] = cum;
                }
            }
        }
    } else {
        // ---- xb part: two rows per block ----
        const int half = tid >> 7;
        const int s = tid & 127;
        const int bk = (blk - 192) * 2 + half;     // 0..5631
        const int b = bk / CIN, r = bk - b * CIN;
        const int lane = s & 31, wid = s >> 5;
        const bool act = (s < SEG);
        float v[WIN];
        #pragma unroll
        for (int pp = 0; pp < WIN; pp++) {
            int m = 22 * pp + r;
            int c = m / 9, w = m - c * 9;
            v[pp] = act ? x[((size_t)b * CIN + c) * TLEN + w * SEG + s] : 0.f;
        }
        #pragma unroll
        for (int pp = 0; pp < WIN; pp++) {
            float t = v[pp];
            #pragma unroll
            for (int m = 16; m >= 1; m >>= 1) t += __shfl_xor_sync(0xffffffffu, t, m);
            if (lane == 0) red2[half][wid * WIN + pp] = t;
        }
        __syncthreads();
        if (s < WIN) {
            float* rd = red2[half];
            float t = rd[s] + rd[WIN + s] + rd[2 * WIN + s] + rd[3 * WIN + s];
            int m = 22 * s + r;
            int c = m / 9;
            atomicAdd(&g_xmean[b * CIN + c], t * (1.f / (float)TLEN));
        }
        if (act) {
            float* dst = g_xb + ((size_t)b * CIN + r) * TLEN + s;
            #pragma unroll
            for (int p = 0; p < WIN; p++) {
                float a = 0.f;
                #pragma unroll
                for (int pp = 0; pp < WIN; pp++)
                    a = fmaf(g_Atb2[p * 9 + pp], v[pp], a);
                dst[p * SEG] = a;
            }
        }
    }
}

// ============================================================
// MAIN: bf16 m16n8k16 mma.sync conv — EXACT R13 mainloop (known best).
// grid (9, 512), 128 threads. Warp (wm, wn): 64 t x 32 o.
// ============================================================
#define DYN_SMEM ((4224 + 4096 + 128) * 4)   // y pairs + 2x weight buf (=C table) + s_part

__global__ void __launch_bounds__(128) k_conv5(const float* __restrict__ x) {
    extern __shared__ float sm[];
    float* y_s = sm;                  // [22][192] bf16x2 pairs
    float* w_s = sm + 4224;           // [2][2048] b32 fragments; reused as C table [64][64]
    float* s_part = sm + 4224 + 4096; // [2][64]
    __shared__ float s_q[64], s_tg[64], s_tb[64];

    const int w = blockIdx.x;
    const int bb = blockIdx.y;
    const int tid = threadIdx.x;
    const int wid = tid >> 5, lane = tid & 31;
    const int wm = wid & 1, wn = wid >> 1;
    const int g = lane >> 2, tig = lane & 3;
    const int t0 = w * SEG - 31;
    const float* src = ((bb >> 8) ? g_xb : x) + (size_t)(bb & 255) * CIN * TLEN;

    // y halo tile as overlapping bf16x2 pairs (187 valid positions, rest zero)
    uint32_t* yu = (uint32_t*)y_s;
    for (int idx = tid; idx < CIN * 192; idx += 128) {
        int c = idx / 192, tt = idx - c * 192;
        int gt = t0 + tt;
        float v0 = (gt >= 0 && gt < TLEN && tt < 187) ? src[(size_t)c * TLEN + gt] : 0.f;
        float v1 = (gt + 1 >= 0 && gt + 1 < TLEN && tt + 1 < 187) ? src[(size_t)c * TLEN + gt + 1] : 0.f;
        yu[idx] = pack_bf(v0, v1);
    }
    // first channel's weights
    {
        const float4* s4 = (const float4*)g_w3;
        float4* d4 = (float4*)w_s;
        #pragma unroll
        for (int j = 0; j < 4; j++) d4[j * 128 + tid] = s4[j * 128 + tid];
    }
    if (tid < 64) { s_q[tid] = g_C[tid * 64 + 63]; s_tg[tid] = g_tg[tid]; s_tb[tid] = g_tb[tid]; }
    __syncthreads();

    float acc[4][4][4];
    #pragma unroll
    for (int m = 0; m < 4; m++)
        #pragma unroll
        for (int nt = 0; nt < 4; nt++)
            #pragma unroll
            for (int j = 0; j < 4; j++) acc[m][nt][j] = 0.f;

    for (int c = 0; c < CIN; c++) {
        float4 pf[4];
        if (c < CIN - 1) {
            const float4* s4 = (const float4*)(g_w3 + (c + 1) * 2048);
            #pragma unroll
            for (int j = 0; j < 4; j++) pf[j] = s4[j * 128 + tid];
        }
        const uint32_t* ya = yu + c * 192 + wm * 64 + g + 2 * tig;
        const uint32_t* wb = (const uint32_t*)w_s + (c & 1) * 2048 + wn * 256 + lane * 2;

        #pragma unroll
        for (int chunk = 0; chunk < 4; chunk++) {
            uint32_t a[4][4];
            #pragma unroll
            for (int m = 0; m < 4; m++) {
                const uint32_t* p = ya + m * 16 + chunk * 16;
                uint32_t p0 = p[0], p1 = p[8], p2 = p[16];
                a[m][0] = p0; a[m][1] = p1; a[m][2] = p1; a[m][3] = p2;
            }
            #pragma unroll
            for (int nt = 0; nt < 4; nt++) {
                uint2 bv = *(const uint2*)(wb + chunk * 512 + nt * 64);
                #pragma unroll
                for (int m = 0; m < 4; m++)
                    mma16(acc[m][nt], a[m], bv.x, bv.y);
            }
        }
        __syncthreads();
        if (c < CIN - 1) {
            float4* d4 = (float4*)(w_s + ((c + 1) & 1) * 2048);
            #pragma unroll
            for (int j = 0; j < 4; j++) d4[j * 128 + tid] = pf[j];
            __syncthreads();
        }
    }

    // ---- epilogue ----
    const bool edge = (w == 0) || (w == WIN - 1);
    if (edge) {
        for (int j = tid; j < 4096; j += 128) w_s[j] = g_C[j];
    }
    __syncthreads();

    const int tg_base = w * SEG;
    #pragma unroll
    for (int nt = 0; nt < 4; nt++) {
        int o0 = wn * 32 + nt * 8 + 2 * tig, o1 = o0 + 1;
        float tg0 = s_tg[o0], tb0_ = s_tb[o0], tg1 = s_tg[o1], tb1_ = s_tb[o1];
        float q0 = s_q[o0], q1 = s_q[o1];
        float s0 = 0.f, s1 = 0.f;
        #pragma unroll
        for (int m = 0; m < 4; m++) {
            int t_a = wm * 64 + m * 16 + g;
            int t_b = t_a + 8;
            float b0a = q0, b1a = q1, b0b = q0, b1b = q1;
            if (edge) {
                int tag = tg_base + t_a;
                int kmin = 31 - tag; kmin = kmin < 0 ? 0 : kmin;
                int kx = 1156 - tag; kx = kx > 63 ? 63 : kx;
                b0a = w_s[o0 * 64 + kx] - w_s[o0 * 64 + kmin];
                b1a = w_s[o1 * 64 + kx] - w_s[o1 * 64 + kmin];
                int tbg = tag + 8;
                int kminb = 31 - tbg; kminb = kminb < 0 ? 0 : kminb;
                int kxb = 1156 - tbg; kxb = kxb > 63 ? 63 : kxb;
                b0b = w_s[o0 * 64 + kxb] - w_s[o0 * 64 + kminb];
                b1b = w_s[o1 * 64 + kxb] - w_s[o1 * 64 + kminb];
            }
            if (t_a < SEG) {
                s0 += gelu_exact(fmaf(acc[m][nt][0] + b0a, tg0, tb0_));
                s1 += gelu_exact(fmaf(acc[m][nt][1] + b1a, tg1, tb1_));
            }
            if (t_b < SEG) {
                s0 += gelu_exact(fmaf(acc[m][nt][2] + b0b, tg0, tb0_));
                s1 += gelu_exact(fmaf(acc[m][nt][3] + b1b, tg1, tb1_));
            }
        }
        s0 += __shfl_xor_sync(0xffffffffu, s0, 4);
        s0 += __shfl_xor_sync(0xffffffffu, s0, 8);
        s0 += __shfl_xor_sync(0xffffffffu, s0, 16);
        s1 += __shfl_xor_sync(0xffffffffu, s1, 4);
        s1 += __shfl_xor_sync(0xffffffffu, s1, 8);
        s1 += __shfl_xor_sync(0xffffffffu, s1, 16);
        if (g == 0) {
            s_part[wm * 64 + o0] = s0;
            s_part[wm * 64 + o1] = s1;
        }
    }
    __syncthreads();
    if (tid < 64)
        g_pool[(tid * 9 + w) * (2 * BATCH) + bb] = (s_part[tid] + s_part[64 + tid]) * 0.008f;
}

// ============================================================
// final FCs + fuse — parallel: 8 blocks x (32 b x 8 j-groups)
// ============================================================
__global__ void k_fc(const float* __restrict__ fc_a_b,
                     const float* __restrict__ fc_b_w, const float* __restrict__ fc_b_b,
                     const float* __restrict__ fc_c_w, const float* __restrict__ fc_c_b,
                     const float* __restrict__ fuse_w, const float* __restrict__ fuse_b,
                     float* __restrict__ out)
{
    __shared__ float sA[NCLS * 576];
    __shared__ float sB[NCLS * 576];
    __shared__ float red[256][8];
    const int tid = threadIdx.x;
    for (int idx = tid; idx < NCLS * 576; idx += 256) {
        sA[idx] = g_fcA[idx];
        sB[idx] = fc_b_w[idx];
    }
    __syncthreads();
    const int bl = tid & 31, jg = tid >> 5;
    const int b = blockIdx.x * 32 + bl;
    float la[4] = {0.f, 0.f, 0.f, 0.f}, lb[4] = {0.f, 0.f, 0.f, 0.f};
    const int j0 = jg * 72;
    for (int j = j0; j < j0 + 72; j++) {
        float va = g_pool[j * (2 * BATCH) + b];
        float vb = g_pool[j * (2 * BATCH) + BATCH + b];
        #pragma unroll
        for (int n = 0; n < 4; n++) {
            la[n] = fmaf(sA[n * 576 + j], va, la[n]);
            lb[n] = fmaf(sB[n * 576 + j], vb, lb[n]);
        }
    }
    #pragma unroll
    for (int n = 0; n < 4; n++) { red[tid][n] = la[n]; red[tid][4 + n] = lb[n]; }
    __syncthreads();
    if (jg == 0) {
        #pragma unroll
        for (int n = 0; n < 4; n++) { la[n] += fc_a_b[n]; lb[n] += fc_b_b[n]; }
        for (int gg = 1; gg < 8; gg++) {
            #pragma unroll
            for (int n = 0; n < 4; n++) {
                la[n] += red[gg * 32 + bl][n];
                lb[n] += red[gg * 32 + bl][4 + n];
            }
        }
        float lc[4];
        #pragma unroll
        for (int n = 0; n < 4; n++) lc[n] = fc_c_b[n];
        for (int c = 0; c < CIN; c++) {
            float v = g_xmean[b * CIN + c];
            #pragma unroll
            for (int n = 0; n < 4; n++) lc[n] = fmaf(fc_c_w[n * CIN + c], v, lc[n]);
        }
        #pragma unroll
        for (int n = 0; n < 4; n++) {
            float o = fuse_b[n];
            #pragma unroll
            for (int m = 0; m < 4; m++) {
                o = fmaf(fuse_w[n * 12 + m], la[m], o);
                o = fmaf(fuse_w[n * 12 + 4 + m], lb[m], o);
                o = fmaf(fuse_w[n * 12 + 8 + m], lc[m], o);
            }
            out[b * 4 + n] = o;
        }
    }
}

// ============================================================
// launch
// ============================================================
extern "C" void kernel_launch(void* const* d_in, const int* in_sizes, int n_in,
                              void* d_out, int out_size) {
    const float* x        = (const float*)d_in[0];
    const float* edge_w   = (const float*)d_in[1];
    const float* sconv_w  = (const float*)d_in[2];
    const float* sbn_g    = (const float*)d_in[3];
    const float* sbn_b    = (const float*)d_in[4];
    const float* sbn_m    = (const float*)d_in[5];
    const float* sbn_v    = (const float*)d_in[6];
    const float* tconv_w  = (const float*)d_in[7];
    const float* tbn_g    = (const float*)d_in[8];
    const float* tbn_b    = (const float*)d_in[9];
    const float* tbn_m    = (const float*)d_in[10];
    const float* tbn_v    = (const float*)d_in[11];
    const float* adj_a    = (const float*)d_in[12];
    const float* adj_b    = (const float*)d_in[13];
    const float* fc_a_w   = (const float*)d_in[14];
    const float* fc_a_b   = (const float*)d_in[15];
    const float* fc_b_w   = (const float*)d_in[16];
    const float* fc_b_b   = (const float*)d_in[17];
    const float* fc_c_w   = (const float*)d_in[18];
    const float* fc_c_b   = (const float*)d_in[19];
    const float* fuse_w   = (const float*)d_in[20];
    const float* fuse_b   = (const float*)d_in[21];
    float* out = (float*)d_out;

    cudaFuncSetAttribute(k_conv5, cudaFuncAttributeMaxDynamicSharedMemorySize, DYN_SMEM);

    k_prep<<<1, 256>>>(edge_w, sconv_w, sbn_g, sbn_b, sbn_m, sbn_v,
                       tbn_g, tbn_b, tbn_m, tbn_v, adj_a, adj_b, fc_a_w, out);
    k_fx<<<192 + 2816, 256>>>(tconv_w, x);
    k_conv5<<<dim3(WIN, 2 * BATCH), 128, DYN_SMEM>>>(x);
    k_fc<<<8, 256>>>(fc_a_b, fc_b_w, fc_b_b, fc_c_w, fc_c_b, fuse_w, fuse_b, out);
}

// round 16
// speedup vs baseline: 1.1520x; 1.0407x over previous
#include <cuda_runtime.h>
#include <math.h>
#include <stdint.h>

// ---------------- problem constants ----------------
#define BATCH 256
#define CIN   22
#define WIN   9
#define SEG   125
#define OUTC  64
#define KS    63
#define NCLS  4
#define TLEN  1125          // WIN*SEG
#define NEDGE 231           // 22*21/2

// ---------------- device scratch ----------------
__device__ float g_W1[OUTC * CIN];
__device__ float g_sb[OUTC];
__device__ float g_tg[OUTC];
__device__ float g_tb[OUTC];
__device__ float g_Atb2[WIN * WIN];
__device__ float g_fcA[NCLS * OUTC * WIN];
__device__ float g_xb[BATCH * CIN * TLEN];
__device__ float g_w3[CIN * 2048];               // bf16x2 weights in m16n8k16 B-frag layout
__device__ float g_C[OUTC * (KS + 1)];           // bias cumsum [o][64]
__device__ float g_pool[576 * 2 * BATCH];        // TRANSPOSED: [o*9+w][bb]
__device__ float g_xmean[BATCH * CIN];

// ---------------- helpers ----------------
__device__ __forceinline__ float gelu_exact(float x) {
    return 0.5f * x * (1.f + erff(x * 0.70710678118654752440f));
}
// pack two floats into bf16x2: lo -> bits[15:0], hi -> bits[31:16]
__device__ __forceinline__ uint32_t pack_bf(float lo, float hi) {
    uint32_t r; asm("cvt.rn.bf16x2.f32 %0, %1, %2;" : "=r"(r) : "f"(hi), "f"(lo)); return r;
}
// m16n8k16 bf16 warp MMA (row.col), D += A*B
__device__ __forceinline__ void mma16(float* d, const uint32_t* a, uint32_t b0, uint32_t b1) {
    asm volatile(
        "mma.sync.aligned.m16n8k16.row.col.f32.bf16.bf16.f32 "
        "{%0,%1,%2,%3}, {%4,%5,%6,%7}, {%8,%9}, {%0,%1,%2,%3};"
        : "+f"(d[0]), "+f"(d[1]), "+f"(d[2]), "+f"(d[3])
        : "r"(a[0]), "r"(a[1]), "r"(a[2]), "r"(a[3]), "r"(b0), "r"(b1));
}

// ============================================================
// Kernel 0: small precompute (+ zero g_xmean for the fused mean)
// ============================================================
__global__ void k_prep(const float* __restrict__ ew,
                       const float* __restrict__ sconv_w,
                       const float* __restrict__ sbn_g, const float* __restrict__ sbn_b,
                       const float* __restrict__ sbn_m, const float* __restrict__ sbn_v,
                       const float* __restrict__ tbn_g, const float* __restrict__ tbn_b,
                       const float* __restrict__ tbn_m, const float* __restrict__ tbn_v,
                       const float* __restrict__ adj_after,
                       const float* __restrict__ adj_before,
                       const float* __restrict__ fc_a_w,
                       float* __restrict__ out)
{
    __shared__ float A[484], As[484], As2[484], d22[22];
    __shared__ float Mt[81], At[81], At2[81], d9[9];
    const int tid = threadIdx.x;

    for (int idx = tid; idx < BATCH * CIN; idx += 256) g_xmean[idx] = 0.f;

    for (int idx = tid; idx < 484; idx += 256) {
        int i = idx / 22, j = idx - i * 22;
        A[idx] = (i == j) ? 1.f : 0.f;
    }
    __syncthreads();
    if (tid < NEDGE) {
        int e = tid, i = 1, base = 0;
        while (e >= base + i) { base += i; i++; }
        int j = e - base;
        float v = ew[tid];
        A[i * 22 + j] = v; A[j * 22 + i] = v;
    }
    __syncthreads();
    if (tid < 22) {
        float s = 0.f;
        for (int j = 0; j < 22; j++) s += A[tid * 22 + j];
        d22[tid] = rsqrtf(s);
    }
    __syncthreads();
    for (int idx = tid; idx < 484; idx += 256) {
        int i = idx / 22, j = idx - i * 22;
        As[idx] = A[idx] * d22[i] * d22[j];
    }
    __syncthreads();
    for (int idx = tid; idx < 484; idx += 256) {
        out[1024 + idx] = As[idx];
        out[1670 + idx] = As[idx];
        int i = idx / 22, j = idx - i * 22;
        float s = 0.f;
        for (int k = 0; k < 22; k++) s += As[i * 22 + k] * As[k * 22 + j];
        As2[idx] = s;
    }
    __syncthreads();

    for (int idx = tid; idx < OUTC * CIN; idx += 256) {
        int o = idx / CIN, c = idx - o * CIN;
        float s = 0.f;
        for (int c2 = 0; c2 < 22; c2++) s += sconv_w[o * CIN + c2] * As2[c2 * 22 + c];
        float sg = sbn_g[o] * rsqrtf(sbn_v[o] + 1e-5f);
        g_W1[idx] = sg * s;
    }
    if (tid < OUTC) {
        float sg = sbn_g[tid] * rsqrtf(sbn_v[tid] + 1e-5f);
        g_sb[tid] = sbn_b[tid] - sbn_m[tid] * sg;
        float tg = tbn_g[tid] * rsqrtf(tbn_v[tid] + 1e-5f);
        g_tg[tid] = tg;
        g_tb[tid] = tbn_b[tid] - tbn_m[tid] * tg;
    }

    if (tid < 81) {
        int i = tid / 9, j = tid - i * 9;
        Mt[tid] = 0.5f * (adj_after[i * 9 + j] + adj_after[j * 9 + i]);
    }
    __syncthreads();
    if (tid < 9) {
        float s = 0.f;
        for (int j = 0; j < 9; j++) s += Mt[tid * 9 + j];
        d9[tid] = rsqrtf(s);
    }
    __syncthreads();
    if (tid < 81) {
        int i = tid / 9, j = tid - i * 9;
        At[tid] = Mt[tid] * d9[i] * d9[j];
        out[1508 + tid] = At[tid];
    }
    __syncthreads();
    if (tid < 81) {
        int i = tid / 9, j = tid - i * 9;
        float s = 0.f;
        for (int k = 0; k < 9; k++) s += At[i * 9 + k] * At[k * 9 + j];
        At2[tid] = s;
    }
    __syncthreads();
    for (int idx = tid; idx < NCLS * OUTC * WIN; idx += 256) {
        int n = idx / (OUTC * WIN);
        int rem = idx - n * OUTC * WIN;
        int o = rem / WIN, w = rem - o * WIN;
        float s = 0.f;
        for (int wp = 0; wp < 9; wp++) s += fc_a_w[n * 576 + o * 9 + wp] * At2[wp * 9 + w];
        g_fcA[idx] = s;
    }
    __syncthreads();

    if (tid < 81) {
        int i = tid / 9, j = tid - i * 9;
        Mt[tid] = 0.5f * (adj_before[i * 9 + j] + adj_before[j * 9 + i]);
    }
    __syncthreads();
    if (tid < 9) {
        float s = 0.f;
        for (int j = 0; j < 9; j++) s += Mt[tid * 9 + j];
        d9[tid] = rsqrtf(s);
    }
    __syncthreads();
    if (tid < 81) {
        int i = tid / 9, j = tid - i * 9;
        At[tid] = Mt[tid] * d9[i] * d9[j];
        out[1589 + tid] = At[tid];
    }
    __syncthreads();
    if (tid < 81) {
        int i = tid / 9, j = tid - i * 9;
        float s = 0.f;
        for (int k = 0; k < 9; k++) s += At[i * 9 + k] * At[k * 9 + j];
        g_Atb2[tid] = s;
    }
}

// ============================================================
// k_fx: MERGED fold + xb (independent; co-scheduled in one launch)
// blocks 0..175:    bf16 B-fragments from tconv_w (x) g_W1
// blocks 176..191:  bias q + in-block cumsum -> g_C
// blocks 192..3007: branch-B time mix, TWO (b,r) rows per block
//                   + fused branch-C mean partials
// ============================================================
__global__ void k_fx(const float* __restrict__ tconv_w,
                     const float* __restrict__ x) {
    __shared__ float sW1[OUTC * CIN];
    __shared__ float ssb[OUTC];
    __shared__ float sq[4][64];
    __shared__ float red2[2][4 * WIN];
    const int blk = blockIdx.x, tid = threadIdx.x;

    if (blk < 192) {
        for (int i = tid; i < OUTC * CIN; i += 256) sW1[i] = g_W1[i];
        if (tid < OUTC) ssb[tid] = g_sb[tid];
        __syncthreads();

        if (blk < 176) {
            int idx = blk * 256 + tid;                 // < CIN*2048 = 45056
            int c = idx >> 11;
            int rem = idx & 2047;
            int chunk = rem >> 9;
            int ntg = (rem >> 6) & 7;
            int lane = (rem >> 1) & 31;
            int r = rem & 1;
            int g = lane >> 2, tig = lane & 3;
            int o = ntg * 8 + g;
            int k0 = chunk * 16 + 2 * tig + 8 * r;
            const float* tw = tconv_w + o * OUTC * KS;
            float s0 = 0.f, s1 = 0.f;
            const bool v0ok = (k0 < KS), v1ok = (k0 + 1 < KS);
            #pragma unroll 8
            for (int i = 0; i < OUTC; i++) {
                float w1 = sW1[i * CIN + c];
                if (v0ok) s0 += tw[i * KS + k0] * w1;
                if (v1ok) s1 += tw[i * KS + k0 + 1] * w1;
            }
            ((uint32_t*)g_w3)[idx] = pack_bf(s0, s1);
        } else {
            int ol = tid >> 6, k = tid & 63;
            int o = (blk - 176) * 4 + ol;
            if (k < KS) {
                const float* wp = tconv_w + o * OUTC * KS + k;
                float s = 0.f;
                #pragma unroll 8
                for (int i = 0; i < OUTC; i++)
                    s += wp[i * KS] * ssb[i];
                sq[ol][k] = s;
            }
            __syncthreads();
            if (k == 0) {
                float cum = 0.f;
                g_C[o * (KS + 1)] = 0.f;
                for (int kk = 0; kk < KS; kk++) {
                    cum += sq[ol][kk];
                    g_C[o * (KS + 1) + kk + 1] = cum;
                }
            }
        }
    } else {
        // ---- xb part: two rows per block ----
        const int half = tid >> 7;
        const int s = tid & 127;
        const int bk = (blk - 192) * 2 + half;     // 0..5631
        const int b = bk / CIN, r = bk - b * CIN;
        const int lane = s & 31, wid = s >> 5;
        const bool act = (s < SEG);
        float v[WIN];
        #pragma unroll
        for (int pp = 0; pp < WIN; pp++) {
            int m = 22 * pp + r;
            int c = m / 9, w = m - c * 9;
            v[pp] = act ? x[((size_t)b * CIN + c) * TLEN + w * SEG + s] : 0.f;
        }
        #pragma unroll
        for (int pp = 0; pp < WIN; pp++) {
            float t = v[pp];
            #pragma unroll
            for (int m = 16; m >= 1; m >>= 1) t += __shfl_xor_sync(0xffffffffu, t, m);
            if (lane == 0) red2[half][wid * WIN + pp] = t;
        }
        __syncthreads();
        if (s < WIN) {
            float* rd = red2[half];
            float t = rd[s] + rd[WIN + s] + rd[2 * WIN + s] + rd[3 * WIN + s];
            int m = 22 * s + r;
            int c = m / 9;
            atomicAdd(&g_xmean[b * CIN + c], t * (1.f / (float)TLEN));
        }
        if (act) {
            float* dst = g_xb + ((size_t)b * CIN + r) * TLEN + s;
            #pragma unroll
            for (int p = 0; p < WIN; p++) {
                float a = 0.f;
                #pragma unroll
                for (int pp = 0; pp < WIN; pp++)
                    a = fmaf(g_Atb2[p * 9 + pp], v[pp], a);
                dst[p * SEG] = a;
            }
        }
    }
}

// ============================================================
// MAIN: bf16 m16n8k16 mma.sync conv — EXACT R13 mainloop (known best).
// grid (9, 512), 128 threads. Warp (wm, wn): 64 t x 32 o.
// ============================================================
#define DYN_SMEM ((4224 + 4096 + 128) * 4)   // y pairs + 2x weight buf (=C table) + s_part

__global__ void __launch_bounds__(128) k_conv5(const float* __restrict__ x) {
    extern __shared__ float sm[];
    float* y_s = sm;                  // [22][192] bf16x2 pairs
    float* w_s = sm + 4224;           // [2][2048] b32 fragments; reused as C table [64][64]
    float* s_part = sm + 4224 + 4096; // [2][64]
    __shared__ float s_q[64], s_tg[64], s_tb[64];

    const int w = blockIdx.x;
    const int bb = blockIdx.y;
    const int tid = threadIdx.x;
    const int wid = tid >> 5, lane = tid & 31;
    const int wm = wid & 1, wn = wid >> 1;
    const int g = lane >> 2, tig = lane & 3;
    const int t0 = w * SEG - 31;
    const float* src = ((bb >> 8) ? g_xb : x) + (size_t)(bb & 255) * CIN * TLEN;

    // y halo tile as overlapping bf16x2 pairs (187 valid positions, rest zero)
    uint32_t* yu = (uint32_t*)y_s;
    for (int idx = tid; idx < CIN * 192; idx += 128) {
        int c = idx / 192, tt = idx - c * 192;
        int gt = t0 + tt;
        float v0 = (gt >= 0 && gt < TLEN && tt < 187) ? src[(size_t)c * TLEN + gt] : 0.f;
        float v1 = (gt + 1 >= 0 && gt + 1 < TLEN && tt + 1 < 187) ? src[(size_t)c * TLEN + gt + 1] : 0.f;
        yu[idx] = pack_bf(v0, v1);
    }
    // first channel's weights
    {
        const float4* s4 = (const float4*)g_w3;
        float4* d4 = (float4*)w_s;
        #pragma unroll
        for (int j = 0; j < 4; j++) d4[j * 128 + tid] = s4[j * 128 + tid];
    }
    if (tid < 64) { s_q[tid] = g_C[tid * 64 + 63]; s_tg[tid] = g_tg[tid]; s_tb[tid] = g_tb[tid]; }
    __syncthreads();

    float acc[4][4][4];
    #pragma unroll
    for (int m = 0; m < 4; m++)
        #pragma unroll
        for (int nt = 0; nt < 4; nt++)
            #pragma unroll
            for (int j = 0; j < 4; j++) acc[m][nt][j] = 0.f;

    for (int c = 0; c < CIN; c++) {
        float4 pf[4];
        if (c < CIN - 1) {
            const float4* s4 = (const float4*)(g_w3 + (c + 1) * 2048);
            #pragma unroll
            for (int j = 0; j < 4; j++) pf[j] = s4[j * 128 + tid];
        }
        const uint32_t* ya = yu + c * 192 + wm * 64 + g + 2 * tig;
        const uint32_t* wb = (const uint32_t*)w_s + (c & 1) * 2048 + wn * 256 + lane * 2;

        #pragma unroll
        for (int chunk = 0; chunk < 4; chunk++) {
            uint32_t a[4][4];
            #pragma unroll
            for (int m = 0; m < 4; m++) {
                const uint32_t* p = ya + m * 16 + chunk * 16;
                uint32_t p0 = p[0], p1 = p[8], p2 = p[16];
                a[m][0] = p0; a[m][1] = p1; a[m][2] = p1; a[m][3] = p2;
            }
            #pragma unroll
            for (int nt = 0; nt < 4; nt++) {
                uint2 bv = *(const uint2*)(wb + chunk * 512 + nt * 64);
                #pragma unroll
                for (int m = 0; m < 4; m++)
                    mma16(acc[m][nt], a[m], bv.x, bv.y);
            }
        }
        __syncthreads();
        if (c < CIN - 1) {
            float4* d4 = (float4*)(w_s + ((c + 1) & 1) * 2048);
            #pragma unroll
            for (int j = 0; j < 4; j++) d4[j * 128 + tid] = pf[j];
            __syncthreads();
        }
    }

    // ---- epilogue ----
    const bool edge = (w == 0) || (w == WIN - 1);
    if (edge) {
        for (int j = tid; j < 4096; j += 128) w_s[j] = g_C[j];
    }
    __syncthreads();

    const int tg_base = w * SEG;
    #pragma unroll
    for (int nt = 0; nt < 4; nt++) {
        int o0 = wn * 32 + nt * 8 + 2 * tig, o1 = o0 + 1;
        float tg0 = s_tg[o0], tb0_ = s_tb[o0], tg1 = s_tg[o1], tb1_ = s_tb[o1];
        float q0 = s_q[o0], q1 = s_q[o1];
        float s0 = 0.f, s1 = 0.f;
        #pragma unroll
        for (int m = 0; m < 4; m++) {
            int t_a = wm * 64 + m * 16 + g;
            int t_b = t_a + 8;
            float b0a = q0, b1a = q1, b0b = q0, b1b = q1;
            if (edge) {
                int tag = tg_base + t_a;
                int kmin = 31 - tag; kmin = kmin < 0 ? 0 : kmin;
                int kx = 1156 - tag; kx = kx > 63 ? 63 : kx;
                b0a = w_s[o0 * 64 + kx] - w_s[o0 * 64 + kmin];
                b1a = w_s[o1 * 64 + kx] - w_s[o1 * 64 + kmin];
                int tbg = tag + 8;
                int kminb = 31 - tbg; kminb = kminb < 0 ? 0 : kminb;
                int kxb = 1156 - tbg; kxb = kxb > 63 ? 63 : kxb;
                b0b = w_s[o0 * 64 + kxb] - w_s[o0 * 64 + kminb];
                b1b = w_s[o1 * 64 + kxb] - w_s[o1 * 64 + kminb];
            }
            if (t_a < SEG) {
                s0 += gelu_exact(fmaf(acc[m][nt][0] + b0a, tg0, tb0_));
                s1 += gelu_exact(fmaf(acc[m][nt][1] + b1a, tg1, tb1_));
            }
            if (t_b < SEG) {
                s0 += gelu_exact(fmaf(acc[m][nt][2] + b0b, tg0, tb0_));
                s1 += gelu_exact(fmaf(acc[m][nt][3] + b1b, tg1, tb1_));
            }
        }
        s0 += __shfl_xor_sync(0xffffffffu, s0, 4);
        s0 += __shfl_xor_sync(0xffffffffu, s0, 8);
        s0 += __shfl_xor_sync(0xffffffffu, s0, 16);
        s1 += __shfl_xor_sync(0xffffffffu, s1, 4);
        s1 += __shfl_xor_sync(0xffffffffu, s1, 8);
        s1 += __shfl_xor_sync(0xffffffffu, s1, 16);
        if (g == 0) {
            s_part[wm * 64 + o0] = s0;
            s_part[wm * 64 + o1] = s1;
        }
    }
    __syncthreads();
    if (tid < 64)
        g_pool[(tid * 9 + w) * (2 * BATCH) + bb] = (s_part[tid] + s_part[64 + tid]) * 0.008f;
}

// ============================================================
// final FCs + fuse — 8 blocks x 1024 threads (32 b x 32 j-groups of 18)
// ============================================================
__global__ void __launch_bounds__(1024) k_fc(
                     const float* __restrict__ fc_a_b,
                     const float* __restrict__ fc_b_w, const float* __restrict__ fc_b_b,
                     const float* __restrict__ fc_c_w, const float* __restrict__ fc_c_b,
                     const float* __restrict__ fuse_w, const float* __restrict__ fuse_b,
                     float* __restrict__ out)
{
    __shared__ float sA[NCLS * 576];
    __shared__ float sB[NCLS * 576];
    __shared__ float red[1024][8];
    const int tid = threadIdx.x;
    for (int idx = tid; idx < NCLS * 576; idx += 1024) {
        sA[idx] = g_fcA[idx];
        sB[idx] = fc_b_w[idx];
    }
    __syncthreads();
    const int bl = tid & 31, jg = tid >> 5;     // jg in 0..31
    const int b = blockIdx.x * 32 + bl;
    float la[4] = {0.f, 0.f, 0.f, 0.f}, lb[4] = {0.f, 0.f, 0.f, 0.f};
    const int j0 = jg * 18;
    #pragma unroll 2
    for (int j = j0; j < j0 + 18; j++) {
        float va = g_pool[j * (2 * BATCH) + b];
        float vb = g_pool[j * (2 * BATCH) + BATCH + b];
        #pragma unroll
        for (int n = 0; n < 4; n++) {
            la[n] = fmaf(sA[n * 576 + j], va, la[n]);
            lb[n] = fmaf(sB[n * 576 + j], vb, lb[n]);
        }
    }
    #pragma unroll
    for (int n = 0; n < 4; n++) { red[tid][n] = la[n]; red[tid][4 + n] = lb[n]; }
    __syncthreads();
    // stage 1: fold groups 8..31 into 0..7
    if (jg < 8) {
        #pragma unroll
        for (int n = 0; n < 8; n++) {
            red[tid][n] += red[(jg + 8) * 32 + bl][n]
                         + red[(jg + 16) * 32 + bl][n]
                         + red[(jg + 24) * 32 + bl][n];
        }
    }
    __syncthreads();
    if (jg == 0) {
        #pragma unroll
        for (int n = 0; n < 4; n++) { la[n] = red[tid][n] + fc_a_b[n]; lb[n] = red[tid][4 + n] + fc_b_b[n]; }
        for (int gg = 1; gg < 8; gg++) {
            #pragma unroll
            for (int n = 0; n < 4; n++) {
                la[n] += red[gg * 32 + bl][n];
                lb[n] += red[gg * 32 + bl][4 + n];
            }
        }
        float lc[4];
        #pragma unroll
        for (int n = 0; n < 4; n++) lc[n] = fc_c_b[n];
        for (int c = 0; c < CIN; c++) {
            float v = g_xmean[b * CIN + c];
            #pragma unroll
            for (int n = 0; n < 4; n++) lc[n] = fmaf(fc_c_w[n * CIN + c], v, lc[n]);
        }
        #pragma unroll
        for (int n = 0; n < 4; n++) {
            float o = fuse_b[n];
            #pragma unroll
            for (int m = 0; m < 4; m++) {
                o = fmaf(fuse_w[n * 12 + m], la[m], o);
                o = fmaf(fuse_w[n * 12 + 4 + m], lb[m], o);
                o = fmaf(fuse_w[n * 12 + 8 + m], lc[m], o);
            }
            out[b * 4 + n] = o;
        }
    }
}

// ============================================================
// launch
// ============================================================
extern "C" void kernel_launch(void* const* d_in, const int* in_sizes, int n_in,
                              void* d_out, int out_size) {
    const float* x        = (const float*)d_in[0];
    const float* edge_w   = (const float*)d_in[1];
    const float* sconv_w  = (const float*)d_in[2];
    const float* sbn_g    = (const float*)d_in[3];
    const float* sbn_b    = (const float*)d_in[4];
    const float* sbn_m    = (const float*)d_in[5];
    const float* sbn_v    = (const float*)d_in[6];
    const float* tconv_w  = (const float*)d_in[7];
    const float* tbn_g    = (const float*)d_in[8];
    const float* tbn_b    = (const float*)d_in[9];
    const float* tbn_m    = (const float*)d_in[10];
    const float* tbn_v    = (const float*)d_in[11];
    const float* adj_a    = (const float*)d_in[12];
    const float* adj_b    = (const float*)d_in[13];
    const float* fc_a_w   = (const float*)d_in[14];
    const float* fc_a_b   = (const float*)d_in[15];
    const float* fc_b_w   = (const float*)d_in[16];
    const float* fc_b_b   = (const float*)d_in[17];
    const float* fc_c_w   = (const float*)d_in[18];
    const float* fc_c_b   = (const float*)d_in[19];
    const float* fuse_w   = (const float*)d_in[20];
    const float* fuse_b   = (const float*)d_in[21];
    float* out = (float*)d_out;

    cudaFuncSetAttribute(k_conv5, cudaFuncAttributeMaxDynamicSharedMemorySize, DYN_SMEM);

    k_prep<<<1, 256>>>(edge_w, sconv_w, sbn_g, sbn_b, sbn_m, sbn_v,
                       tbn_g, tbn_b, tbn_m, tbn_v, adj_a, adj_b, fc_a_w, out);
    k_fx<<<192 + 2816, 256>>>(tconv_w, x);
    k_conv5<<<dim3(WIN, 2 * BATCH), 128, DYN_SMEM>>>(x);
    k_fc<<<8, 1024>>>(fc_a_b, fc_b_w, fc_b_b, fc_c_w, fc_c_b, fuse_w, fuse_b, out);
}